// round 13
// baseline (speedup 1.0000x reference)
#include <cuda_runtime.h>
#include <cuda_bf16.h>
#include <math.h>
#include <stdint.h>

// ---------------- problem constants ----------------
#define BATCH 4
#define SEQ   2048
#define DIM   512
#define NHEAD 8
#define HDIM  64
#define FFN   2048
#define MTOT  (BATCH * SEQ)          // 8192 rows
#define QKVW  (3 * DIM)              // 1536

// ---------------- scratch (no allocation allowed) ----------------
__device__ float g_qkv [MTOT * QKVW];
__device__ float g_att [MTOT * DIM];
__device__ float g_y1  [MTOT * DIM];
__device__ float g_x1  [MTOT * DIM];
__device__ float g_h   [MTOT * FFN];
__device__ float g_y2  [MTOT * DIM];
__device__ float g_xr  [MTOT * DIM];       // tf32-rounded x
__device__ float g_wqr [DIM * DIM];
__device__ float g_wkr [DIM * DIM];
__device__ float g_wvr [DIM * DIM];
__device__ float g_wor [DIM * DIM];
__device__ float g_w1r [DIM * FFN];
__device__ float g_w2r [FFN * DIM];

// ---------------- helpers ----------------
__device__ __forceinline__ uint32_t smem_u32(const void* p) {
    uint32_t a;
    asm("{ .reg .u64 t; cvta.to.shared.u64 t, %1; cvt.u32.u64 %0, t; }"
        : "=r"(a) : "l"(p));
    return a;
}
__device__ __forceinline__ uint32_t f2tf(float x) {
    uint32_t r;
    asm("cvt.rna.tf32.f32 %0, %1;" : "=r"(r) : "f"(x));
    return r;
}
__device__ __forceinline__ float tf32r(float x) {
    return __uint_as_float(f2tf(x));
}
__device__ __forceinline__ float gelu_exact(float v) {
    return 0.5f * v * (1.0f + erff(v * 0.70710678118654752f));
}
__device__ __forceinline__ void mma16n8k8(float* c, const uint32_t* a, const uint32_t* b) {
    asm volatile(
        "mma.sync.aligned.m16n8k8.row.col.f32.tf32.tf32.f32 "
        "{%0,%1,%2,%3}, {%4,%5,%6,%7}, {%8,%9}, {%0,%1,%2,%3};"
        : "+f"(c[0]), "+f"(c[1]), "+f"(c[2]), "+f"(c[3])
        : "r"(a[0]), "r"(a[1]), "r"(a[2]), "r"(a[3]), "r"(b[0]), "r"(b[1]));
}

#define CP_ASYNC16(saddr, gptr) \
    asm volatile("cp.async.cg.shared.global [%0], [%1], 16;" \
                 :: "r"(saddr), "l"(gptr) : "memory")
#define CP_COMMIT() asm volatile("cp.async.commit_group;" ::: "memory")
#define CP_WAIT1()  asm volatile("cp.async.wait_group 1;" ::: "memory")
#define CP_WAIT0()  asm volatile("cp.async.wait_group 0;" ::: "memory")

// ---------------- tf32 pre-round passes ----------------
__global__ __launch_bounds__(256) void round_x_kernel(
    const float* __restrict__ src, float* __restrict__ dst, int n4)
{
    int i = blockIdx.x * 256 + threadIdx.x;
    if (i < n4) {
        float4 v = ((const float4*)src)[i];
        v.x = tf32r(v.x); v.y = tf32r(v.y); v.z = tf32r(v.z); v.w = tf32r(v.w);
        ((float4*)dst)[i] = v;
    }
}

// all six weight matrices in one launch (region select by index)
#define W44 (DIM * DIM / 4)    // 65536 float4
#define WF4 (DIM * FFN / 4)    // 262144 float4
__global__ __launch_bounds__(256) void round_w_kernel(
    const float* __restrict__ wq, const float* __restrict__ wk,
    const float* __restrict__ wv, const float* __restrict__ wo,
    const float* __restrict__ w1, const float* __restrict__ w2,
    float* __restrict__ wqr, float* __restrict__ wkr,
    float* __restrict__ wvr, float* __restrict__ wor,
    float* __restrict__ w1r, float* __restrict__ w2r)
{
    int i = blockIdx.x * 256 + threadIdx.x;   // 0 .. 786431
    const float* s; float* d; int j;
    if (i < 4 * W44) {
        int r = i >> 16;                       // W44 == 65536
        j = i & (W44 - 1);
        s = (r == 0) ? wq : (r == 1) ? wk : (r == 2) ? wv : wo;
        d = (r == 0) ? wqr : (r == 1) ? wkr : (r == 2) ? wvr : wor;
    } else {
        int k = i - 4 * W44;
        if (k < WF4) { s = w1; d = w1r; j = k; }
        else         { s = w2; d = w2r; j = k - WF4; }
    }
    float4 v = ((const float4*)s)[j];
    v.x = tf32r(v.x); v.y = tf32r(v.y); v.z = tf32r(v.z); v.w = tf32r(v.w);
    ((float4*)d)[j] = v;
}

// ---------------- tf32 mma.sync GEMM, 3-stage cp.async, 2 CTAs/SM -----------
// A smem: [128 m][36 k-words] ; B smem: [32 k][132 n-words]
// ONE __syncthreads per chunk: issue at iter c targets buffer (c+2)%3, which
// all warps finished consuming before this iteration's barrier.
#define AW 36
#define BW 132
#define ASTG (128 * AW)            // 4608 words
#define BSTG (32 * BW)             // 4224 words
#define STG  (ASTG + BSTG)         // 8832 words
#define GEMM_SMEM (3 * STG * 4)    // 105984 bytes -> 2 CTAs/SM

template<int EPI>
__device__ __forceinline__ void mma_gemm_body(
    const float* __restrict__ A,
    const float* __restrict__ B, int ldb, int bcol,
    const float* __restrict__ biasBlk,
    const float* __restrict__ res,
    float* __restrict__ C, int ldc, int ccol,
    int K)
{
    extern __shared__ uint32_t smu[];
    const uint32_t sb = smem_u32(smu);

    const int tid  = threadIdx.x;
    const int lane = tid & 31;
    const int wid  = tid >> 5;
    const int gid  = lane >> 2;
    const int tig  = lane & 3;
    const int rowBase = blockIdx.y * 128;
    const int mb = (wid & 1) * 64;
    const int nb = (wid >> 1) * 32;

    const int arow = tid >> 3;
    const int aj   = (tid & 7) * 4;
    const int brow = tid >> 5;
    const int bj   = (tid & 31) * 4;

    float acc[4][4][4];
    #pragma unroll
    for (int i = 0; i < 4; i++)
        #pragma unroll
        for (int j = 0; j < 4; j++)
            #pragma unroll
            for (int e = 0; e < 4; e++) acc[i][j][e] = 0.0f;

    const int NC = K >> 5;

    auto issue = [&](int s, int c) {
        const uint32_t ab = sb + (uint32_t)(s * STG) * 4u;
        const uint32_t bb = ab + (uint32_t)ASTG * 4u;
        #pragma unroll
        for (int i = 0; i < 4; i++) {
            const int row = arow + i * 32;
            const float* gp = A + (size_t)(rowBase + row) * K + c * 32 + aj;
            CP_ASYNC16(ab + (uint32_t)(row * AW + aj) * 4u, gp);
        }
        #pragma unroll
        for (int i = 0; i < 4; i++) {
            const int row = brow + i * 8;
            const float* gp = B + (size_t)(c * 32 + row) * ldb + bcol + bj;
            CP_ASYNC16(bb + (uint32_t)(row * BW + bj) * 4u, gp);
        }
        CP_COMMIT();
    };

    issue(0, 0);
    issue(1, 1);

    for (int c = 0; c < NC; c++) {
        if (c + 1 < NC) { CP_WAIT1(); } else { CP_WAIT0(); }
        __syncthreads();                     // chunk c visible; buffer (c+2)%3 free

        if (c + 2 < NC) issue((c + 2) % 3, c + 2);

        const uint32_t* As = (const uint32_t*)smu + (c % 3) * STG;
        const uint32_t* Bs = As + ASTG;
        #pragma unroll
        for (int k8 = 0; k8 < 4; k8++) {
            const int kk = k8 * 8 + tig;
            uint32_t a[4][4], b[4][2];
            #pragma unroll
            for (int mt = 0; mt < 4; mt++) {
                const int m0 = mb + mt * 16 + gid;
                a[mt][0] = As[m0 * AW + kk];
                a[mt][1] = As[(m0 + 8) * AW + kk];
                a[mt][2] = As[m0 * AW + kk + 4];
                a[mt][3] = As[(m0 + 8) * AW + kk + 4];
            }
            #pragma unroll
            for (int nt = 0; nt < 4; nt++) {
                const int cn = nb + nt * 8 + gid;
                b[nt][0] = Bs[kk * BW + cn];
                b[nt][1] = Bs[(kk + 4) * BW + cn];
            }
            #pragma unroll
            for (int mt = 0; mt < 4; mt++)
                #pragma unroll
                for (int nt = 0; nt < 4; nt++)
                    mma16n8k8(acc[mt][nt], a[mt], b[nt]);
        }
    }

    // epilogue
    #pragma unroll
    for (int mt = 0; mt < 4; mt++) {
        const int row0 = rowBase + mb + mt * 16 + gid;
        const int row1 = row0 + 8;
        #pragma unroll
        for (int nt = 0; nt < 4; nt++) {
            const int jc  = nb + nt * 8 + tig * 2;
            const int col = ccol + jc;
            const float b0 = biasBlk[jc], b1 = biasBlk[jc + 1];
            float v0 = acc[mt][nt][0] + b0;
            float v1 = acc[mt][nt][1] + b1;
            float v2 = acc[mt][nt][2] + b0;
            float v3 = acc[mt][nt][3] + b1;
            if (EPI == 1) {
                const float* rp0 = res + (size_t)row0 * ldc + col;
                const float* rp1 = res + (size_t)row1 * ldc + col;
                v0 += rp0[0]; v1 += rp0[1];
                v2 += rp1[0]; v3 += rp1[1];
            }
            if (EPI == 2) {
                v0 = gelu_exact(v0); v1 = gelu_exact(v1);
                v2 = gelu_exact(v2); v3 = gelu_exact(v3);
            }
            if (EPI == 0 || EPI == 2) {   // output feeds a GEMM/attention: pre-round
                v0 = tf32r(v0); v1 = tf32r(v1);
                v2 = tf32r(v2); v3 = tf32r(v3);
            }
            *(float2*)(C + (size_t)row0 * ldc + col) = make_float2(v0, v1);
            *(float2*)(C + (size_t)row1 * ldc + col) = make_float2(v2, v3);
        }
    }
}

template<int EPI>
__global__ __launch_bounds__(256, 2) void gemm_mma(
    const float* __restrict__ A, const float* __restrict__ B, int ldb,
    const float* __restrict__ bias, const float* __restrict__ res,
    float* __restrict__ C, int ldc, int K)
{
    const int bcol = blockIdx.x * 128;
    mma_gemm_body<EPI>(A, B, ldb, bcol, bias + bcol, res, C, ldc, bcol, K);
}

__global__ __launch_bounds__(256, 2) void qkv_mma(
    const float* __restrict__ x,
    const float* __restrict__ wq, const float* __restrict__ bq,
    const float* __restrict__ wk, const float* __restrict__ bk,
    const float* __restrict__ wv, const float* __restrict__ bv,
    float* __restrict__ qkv)
{
    const int bx  = blockIdx.x;
    const int sel = bx >> 2;
    const float* W  = (sel == 0) ? wq : (sel == 1) ? wk : wv;
    const float* bi = (sel == 0) ? bq : (sel == 1) ? bk : bv;
    const int bcol = (bx & 3) * 128;
    mma_gemm_body<0>(x, W, DIM, bcol, bi + bcol, nullptr, qkv, QKVW, bx * 128, DIM);
}

// ---------------- tensor-core flash attention (tf32 mma, base-2 softmax) ----
#define ALD 68
#define VLD 72
#define ATTN_SMEM ((64 * ALD + 64 * VLD + 128 * ALD) * 4)   // 70656 B
#define QSCALE 0.18033688011112042f   // 0.125 * log2(e)

__global__ __launch_bounds__(256) void attn_tc(
    const float* __restrict__ QKV, float* __restrict__ O)
{
    extern __shared__ uint32_t asm_[];
    uint32_t* Ks = asm_;
    uint32_t* Vs = Ks + 64 * ALD;
    uint32_t* Ps = Vs + 64 * VLD;

    const int tid  = threadIdx.x;
    const int lane = tid & 31;
    const int wid  = tid >> 5;
    const int gid  = lane >> 2;
    const int tig  = lane & 3;
    const int bh = blockIdx.y;
    const int b  = bh >> 3;
    const int h  = bh & 7;
    const int q0 = blockIdx.x * 128;

    const float* base = QKV + (size_t)b * SEQ * QKVW + (size_t)h * HDIM;
    const float* Qb = base;
    const float* Kb = base + DIM;
    const float* Vb = base + 2 * DIM;

    // Q fragments: scale by 0.125*log2e, re-round to tf32 (RNA) once
    uint32_t qa[8][4];
    {
        const float* qr0 = Qb + (size_t)(q0 + wid * 16 + gid) * QKVW;
        const float* qr1 = qr0 + (size_t)8 * QKVW;
        #pragma unroll
        for (int ks = 0; ks < 8; ks++) {
            const int c = ks * 8 + tig;
            qa[ks][0] = f2tf(qr0[c] * QSCALE);
            qa[ks][1] = f2tf(qr1[c] * QSCALE);
            qa[ks][2] = f2tf(qr0[c + 4] * QSCALE);
            qa[ks][3] = f2tf(qr1[c + 4] * QSCALE);
        }
    }

    float o[8][4];
    #pragma unroll
    for (int i = 0; i < 8; i++)
        #pragma unroll
        for (int j = 0; j < 4; j++) o[i][j] = 0.0f;
    float m0 = -1e30f, m1 = -1e30f, l0 = 0.0f, l1 = 0.0f;

    const int kr = tid >> 2;
    const int dc = (tid & 3) * 16;
    const size_t KVSTEP = (size_t)64 * QKVW;
    const float* kp = Kb + (size_t)kr * QKVW + dc;
    const float* vp = Vb + (size_t)kr * QKVW + dc;

    float4 krg[4], vrg[4];
    #pragma unroll
    for (int i = 0; i < 4; i++) {
        krg[i] = *(const float4*)(kp + i * 4);
        vrg[i] = *(const float4*)(vp + i * 4);
    }

    uint32_t* Pw = Ps + (wid * 16) * ALD;

    for (int t = 0; t < SEQ / 64; t++) {
        #pragma unroll
        for (int i = 0; i < 4; i++) {
            *(float4*)&Ks[kr * ALD + dc + i * 4] = krg[i];
            *(float4*)&Vs[kr * VLD + dc + i * 4] = vrg[i];
        }
        __syncthreads();

        const bool more = (t + 1 < SEQ / 64);
        if (more) {
            kp += KVSTEP;
            #pragma unroll
            for (int i = 0; i < 4; i++) krg[i] = *(const float4*)(kp + i * 4);
        }

        float s[8][4];
        #pragma unroll
        for (int i = 0; i < 8; i++)
            #pragma unroll
            for (int j = 0; j < 4; j++) s[i][j] = 0.0f;
        #pragma unroll
        for (int ks = 0; ks < 8; ks++) {
            const int d = ks * 8 + tig;
            #pragma unroll
            for (int nt = 0; nt < 8; nt++) {
                const int key = nt * 8 + gid;
                uint32_t bf[2] = { Ks[key * ALD + d], Ks[key * ALD + d + 4] };
                mma16n8k8(s[nt], qa[ks], bf);
            }
        }

        // base-2 online softmax
        float cm0 = -1e30f, cm1 = -1e30f;
        #pragma unroll
        for (int nt = 0; nt < 8; nt++) {
            cm0 = fmaxf(cm0, fmaxf(s[nt][0], s[nt][1]));
            cm1 = fmaxf(cm1, fmaxf(s[nt][2], s[nt][3]));
        }
        cm0 = fmaxf(cm0, __shfl_xor_sync(0xffffffffu, cm0, 1));
        cm0 = fmaxf(cm0, __shfl_xor_sync(0xffffffffu, cm0, 2));
        cm1 = fmaxf(cm1, __shfl_xor_sync(0xffffffffu, cm1, 1));
        cm1 = fmaxf(cm1, __shfl_xor_sync(0xffffffffu, cm1, 2));
        const float mn0 = fmaxf(m0, cm0);
        const float mn1 = fmaxf(m1, cm1);
        const float a0 = exp2f(m0 - mn0);
        const float a1 = exp2f(m1 - mn1);
        float ls0 = 0.0f, ls1 = 0.0f;
        #pragma unroll
        for (int nt = 0; nt < 8; nt++) {
            s[nt][0] = exp2f(s[nt][0] - mn0);
            s[nt][1] = exp2f(s[nt][1] - mn0);
            s[nt][2] = exp2f(s[nt][2] - mn1);
            s[nt][3] = exp2f(s[nt][3] - mn1);
            ls0 += s[nt][0] + s[nt][1];
            ls1 += s[nt][2] + s[nt][3];
        }
        ls0 += __shfl_xor_sync(0xffffffffu, ls0, 1);
        ls0 += __shfl_xor_sync(0xffffffffu, ls0, 2);
        ls1 += __shfl_xor_sync(0xffffffffu, ls1, 1);
        ls1 += __shfl_xor_sync(0xffffffffu, ls1, 2);
        l0 = l0 * a0 + ls0;
        l1 = l1 * a1 + ls1;
        m0 = mn0; m1 = mn1;
        #pragma unroll
        for (int nt = 0; nt < 8; nt++) {
            o[nt][0] *= a0; o[nt][1] *= a0;
            o[nt][2] *= a1; o[nt][3] *= a1;
        }

        if (more) {
            vp += KVSTEP;
            #pragma unroll
            for (int i = 0; i < 4; i++) vrg[i] = *(const float4*)(vp + i * 4);
        }

        #pragma unroll
        for (int nt = 0; nt < 8; nt++) {
            const int c = nt * 8 + tig * 2;
            *(uint2*)&Pw[gid * ALD + c]       = make_uint2(f2tf(s[nt][0]), f2tf(s[nt][1]));
            *(uint2*)&Pw[(gid + 8) * ALD + c] = make_uint2(f2tf(s[nt][2]), f2tf(s[nt][3]));
        }
        __syncwarp();

        #pragma unroll
        for (int ks = 0; ks < 8; ks++) {
            const int kk = ks * 8 + tig;
            uint32_t pa[4];
            pa[0] = Pw[gid * ALD + kk];
            pa[1] = Pw[(gid + 8) * ALD + kk];
            pa[2] = Pw[gid * ALD + kk + 4];
            pa[3] = Pw[(gid + 8) * ALD + kk + 4];
            #pragma unroll
            for (int nt = 0; nt < 8; nt++) {
                const int dn = nt * 8 + gid;
                uint32_t bf[2] = { Vs[kk * VLD + dn], Vs[(kk + 4) * VLD + dn] };
                mma16n8k8(o[nt], pa, bf);
            }
        }
        __syncthreads();
    }

    const float i0 = 1.0f / l0;
    const float i1 = 1.0f / l1;
    const int row0 = q0 + wid * 16 + gid;
    float* Ob0 = O + (size_t)(b * SEQ + row0) * DIM + h * HDIM;
    float* Ob1 = Ob0 + (size_t)8 * DIM;
    #pragma unroll
    for (int nt = 0; nt < 8; nt++) {
        const int c = nt * 8 + tig * 2;
        *(float2*)(Ob0 + c) = make_float2(tf32r(o[nt][0] * i0), tf32r(o[nt][1] * i0));
        *(float2*)(Ob1 + c) = make_float2(tf32r(o[nt][2] * i1), tf32r(o[nt][3] * i1));
    }
}

// ---------------- layernorm ----------------
template<int RND>
__global__ __launch_bounds__(256) void ln_kernel(
    const float* __restrict__ x, const float* __restrict__ g,
    const float* __restrict__ be, float* __restrict__ out)
{
    const int row = blockIdx.x;
    const int t = threadIdx.x;
    const float* xr = x + (size_t)row * DIM;
    float v0 = xr[t], v1 = xr[t + 256];
    float s = v0 + v1, sq = v0 * v0 + v1 * v1;
    #pragma unroll
    for (int o = 16; o > 0; o >>= 1) {
        s  += __shfl_xor_sync(0xffffffffu, s, o);
        sq += __shfl_xor_sync(0xffffffffu, sq, o);
    }
    __shared__ float ps[8], pq[8];
    __shared__ float mu_s, inv_s;
    if ((t & 31) == 0) { ps[t >> 5] = s; pq[t >> 5] = sq; }
    __syncthreads();
    if (t == 0) {
        float S = 0.0f, Qq = 0.0f;
        #pragma unroll
        for (int i = 0; i < 8; i++) { S += ps[i]; Qq += pq[i]; }
        float mu = S * (1.0f / DIM);
        float var = Qq * (1.0f / DIM) - mu * mu;
        mu_s = mu;
        inv_s = rsqrtf(var + 1e-5f);
    }
    __syncthreads();
    float mu = mu_s, inv = inv_s;
    float w0 = (v0 - mu) * inv * g[t]       + be[t];
    float w1 = (v1 - mu) * inv * g[t + 256] + be[t + 256];
    if (RND) { w0 = tf32r(w0); w1 = tf32r(w1); }
    out[(size_t)row * DIM + t]       = w0;
    out[(size_t)row * DIM + t + 256] = w1;
}

// ---------------- launch ----------------
extern "C" void kernel_launch(void* const* d_in, const int* in_sizes, int n_in,
                              void* d_out, int out_size)
{
    const float* x   = (const float*)d_in[0];
    const float* wq  = (const float*)d_in[1];
    const float* bq  = (const float*)d_in[2];
    const float* wk  = (const float*)d_in[3];
    const float* bk  = (const float*)d_in[4];
    const float* wv  = (const float*)d_in[5];
    const float* bv  = (const float*)d_in[6];
    const float* wo  = (const float*)d_in[7];
    const float* bo  = (const float*)d_in[8];
    const float* w1  = (const float*)d_in[9];
    const float* b1  = (const float*)d_in[10];
    const float* w2  = (const float*)d_in[11];
    const float* b2  = (const float*)d_in[12];
    const float* g1  = (const float*)d_in[13];
    const float* be1 = (const float*)d_in[14];
    const float* g2  = (const float*)d_in[15];
    const float* be2 = (const float*)d_in[16];
    float* out = (float*)d_out;

    float *qkv, *att, *y1, *x1, *hbuf, *y2;
    float *xr, *wqr, *wkr, *wvr, *wor, *w1r, *w2r;
    cudaGetSymbolAddress((void**)&qkv,  g_qkv);
    cudaGetSymbolAddress((void**)&att,  g_att);
    cudaGetSymbolAddress((void**)&y1,   g_y1);
    cudaGetSymbolAddress((void**)&x1,   g_x1);
    cudaGetSymbolAddress((void**)&hbuf, g_h);
    cudaGetSymbolAddress((void**)&y2,   g_y2);
    cudaGetSymbolAddress((void**)&xr,   g_xr);
    cudaGetSymbolAddress((void**)&wqr,  g_wqr);
    cudaGetSymbolAddress((void**)&wkr,  g_wkr);
    cudaGetSymbolAddress((void**)&wvr,  g_wvr);
    cudaGetSymbolAddress((void**)&wor,  g_wor);
    cudaGetSymbolAddress((void**)&w1r,  g_w1r);
    cudaGetSymbolAddress((void**)&w2r,  g_w2r);

    cudaFuncSetAttribute(attn_tc,
                         cudaFuncAttributeMaxDynamicSharedMemorySize, ATTN_SMEM);
    cudaFuncSetAttribute(qkv_mma,
                         cudaFuncAttributeMaxDynamicSharedMemorySize, GEMM_SMEM);
    cudaFuncSetAttribute(gemm_mma<1>,
                         cudaFuncAttributeMaxDynamicSharedMemorySize, GEMM_SMEM);
    cudaFuncSetAttribute(gemm_mma<2>,
                         cudaFuncAttributeMaxDynamicSharedMemorySize, GEMM_SMEM);

    // pre-round all GEMM operands (RNA tf32): 2 launches
    round_x_kernel<<<(MTOT * DIM / 4 + 255) / 256, 256>>>(x, xr, MTOT * DIM / 4);
    round_w_kernel<<<(4 * W44 + 2 * WF4 + 255) / 256, 256>>>(
        wq, wk, wv, wo, w1, w2, wqr, wkr, wvr, wor, w1r, w2r);

    const int MB = MTOT / 128;   // 64

    // fused QKV projection (output rounded in epilogue)
    qkv_mma<<<dim3(12, MB), 256, GEMM_SMEM>>>(xr, wqr, bq, wkr, bk, wvr, bv, qkv);

    // tensor-core flash attention (output rounded at write)
    attn_tc<<<dim3(SEQ / 128, BATCH * NHEAD), 256, ATTN_SMEM>>>(qkv, att);

    // output projection + residual (res = ORIGINAL x), LN1 (rounds x1)
    gemm_mma<1><<<dim3(DIM / 128, MB), 256, GEMM_SMEM>>>(
        att, wor, DIM, bo, x, y1, DIM, DIM);
    ln_kernel<1><<<MTOT, 256>>>(y1, g1, be1, x1);

    // FFN
    gemm_mma<2><<<dim3(FFN / 128, MB), 256, GEMM_SMEM>>>(
        x1, w1r, FFN, b1, nullptr, hbuf, FFN, DIM);
    gemm_mma<1><<<dim3(DIM / 128, MB), 256, GEMM_SMEM>>>(
        hbuf, w2r, DIM, b2, x1, y2, DIM, FFN);
    ln_kernel<0><<<MTOT, 256>>>(y2, g2, be2, out);
}

// round 14
// speedup vs baseline: 1.0668x; 1.0668x over previous
#include <cuda_runtime.h>
#include <cuda_bf16.h>
#include <math.h>
#include <stdint.h>

// ---------------- problem constants ----------------
#define BATCH 4
#define SEQ   2048
#define DIM   512
#define NHEAD 8
#define HDIM  64
#define FFN   2048
#define MTOT  (BATCH * SEQ)          // 8192 rows
#define QKVW  (3 * DIM)              // 1536

// ---------------- scratch (no allocation allowed) ----------------
__device__ float g_qkv [MTOT * QKVW];
__device__ float g_att [MTOT * DIM];
__device__ float g_y1  [MTOT * DIM];
__device__ float g_x1  [MTOT * DIM];
__device__ float g_h   [MTOT * FFN];
__device__ float g_y2  [MTOT * DIM];
__device__ float g_xr  [MTOT * DIM];       // tf32-rounded x
__device__ float g_wqr [DIM * DIM];
__device__ float g_wkr [DIM * DIM];
__device__ float g_wvr [DIM * DIM];
__device__ float g_wor [DIM * DIM];
__device__ float g_w1r [DIM * FFN];
__device__ float g_w2r [FFN * DIM];

// ---------------- helpers ----------------
__device__ __forceinline__ uint32_t smem_u32(const void* p) {
    uint32_t a;
    asm("{ .reg .u64 t; cvta.to.shared.u64 t, %1; cvt.u32.u64 %0, t; }"
        : "=r"(a) : "l"(p));
    return a;
}
__device__ __forceinline__ uint32_t f2tf(float x) {
    uint32_t r;
    asm("cvt.rna.tf32.f32 %0, %1;" : "=r"(r) : "f"(x));
    return r;
}
__device__ __forceinline__ float tf32r(float x) {
    return __uint_as_float(f2tf(x));
}
__device__ __forceinline__ float gelu_exact(float v) {
    return 0.5f * v * (1.0f + erff(v * 0.70710678118654752f));
}
__device__ __forceinline__ void mma16n8k8(float* c, const uint32_t* a, const uint32_t* b) {
    asm volatile(
        "mma.sync.aligned.m16n8k8.row.col.f32.tf32.tf32.f32 "
        "{%0,%1,%2,%3}, {%4,%5,%6,%7}, {%8,%9}, {%0,%1,%2,%3};"
        : "+f"(c[0]), "+f"(c[1]), "+f"(c[2]), "+f"(c[3])
        : "r"(a[0]), "r"(a[1]), "r"(a[2]), "r"(a[3]), "r"(b[0]), "r"(b[1]));
}

#define CP_ASYNC16(saddr, gptr) \
    asm volatile("cp.async.cg.shared.global [%0], [%1], 16;" \
                 :: "r"(saddr), "l"(gptr) : "memory")
#define CP_COMMIT() asm volatile("cp.async.commit_group;" ::: "memory")
#define CP_WAIT1()  asm volatile("cp.async.wait_group 1;" ::: "memory")
#define CP_WAIT0()  asm volatile("cp.async.wait_group 0;" ::: "memory")

// ---------------- tf32 pre-round passes ----------------
__global__ __launch_bounds__(256) void round_x_kernel(
    const float* __restrict__ src, float* __restrict__ dst, int n4)
{
    int i = blockIdx.x * 256 + threadIdx.x;
    if (i < n4) {
        float4 v = ((const float4*)src)[i];
        v.x = tf32r(v.x); v.y = tf32r(v.y); v.z = tf32r(v.z); v.w = tf32r(v.w);
        ((float4*)dst)[i] = v;
    }
}

#define W44 (DIM * DIM / 4)    // 65536 float4
#define WF4 (DIM * FFN / 4)    // 262144 float4
__global__ __launch_bounds__(256) void round_w_kernel(
    const float* __restrict__ wq, const float* __restrict__ wk,
    const float* __restrict__ wv, const float* __restrict__ wo,
    const float* __restrict__ w1, const float* __restrict__ w2,
    float* __restrict__ wqr, float* __restrict__ wkr,
    float* __restrict__ wvr, float* __restrict__ wor,
    float* __restrict__ w1r, float* __restrict__ w2r)
{
    int i = blockIdx.x * 256 + threadIdx.x;
    const float* s; float* d; int j;
    if (i < 4 * W44) {
        int r = i >> 16;
        j = i & (W44 - 1);
        s = (r == 0) ? wq : (r == 1) ? wk : (r == 2) ? wv : wo;
        d = (r == 0) ? wqr : (r == 1) ? wkr : (r == 2) ? wvr : wor;
    } else {
        int k = i - 4 * W44;
        if (k < WF4) { s = w1; d = w1r; j = k; }
        else         { s = w2; d = w2r; j = k - WF4; }
    }
    float4 v = ((const float4*)s)[j];
    v.x = tf32r(v.x); v.y = tf32r(v.y); v.z = tf32r(v.z); v.w = tf32r(v.w);
    ((float4*)d)[j] = v;
}

// ---------------- tf32 mma.sync GEMM, 3-stage cp.async, 2 CTAs/SM -----------
#define AW 36
#define BW 132
#define ASTG (128 * AW)
#define BSTG (32 * BW)
#define STG  (ASTG + BSTG)         // 8832 words
#define GEMM_SMEM (3 * STG * 4)    // 105984 bytes

template<int EPI>
__device__ __forceinline__ void mma_gemm_body(
    const float* __restrict__ A,
    const float* __restrict__ B, int ldb, int bcol,
    const float* __restrict__ biasBlk,
    const float* __restrict__ res,
    float* __restrict__ C, int ldc, int ccol,
    int K)
{
    extern __shared__ uint32_t smu[];
    const uint32_t sb = smem_u32(smu);

    const int tid  = threadIdx.x;
    const int lane = tid & 31;
    const int wid  = tid >> 5;
    const int gid  = lane >> 2;
    const int tig  = lane & 3;
    const int rowBase = blockIdx.y * 128;
    const int mb = (wid & 1) * 64;
    const int nb = (wid >> 1) * 32;

    const int arow = tid >> 3;
    const int aj   = (tid & 7) * 4;
    const int brow = tid >> 5;
    const int bj   = (tid & 31) * 4;

    float acc[4][4][4];
    #pragma unroll
    for (int i = 0; i < 4; i++)
        #pragma unroll
        for (int j = 0; j < 4; j++)
            #pragma unroll
            for (int e = 0; e < 4; e++) acc[i][j][e] = 0.0f;

    const int NC = K >> 5;

    auto issue = [&](int s, int c) {
        const uint32_t ab = sb + (uint32_t)(s * STG) * 4u;
        const uint32_t bb = ab + (uint32_t)ASTG * 4u;
        #pragma unroll
        for (int i = 0; i < 4; i++) {
            const int row = arow + i * 32;
            const float* gp = A + (size_t)(rowBase + row) * K + c * 32 + aj;
            CP_ASYNC16(ab + (uint32_t)(row * AW + aj) * 4u, gp);
        }
        #pragma unroll
        for (int i = 0; i < 4; i++) {
            const int row = brow + i * 8;
            const float* gp = B + (size_t)(c * 32 + row) * ldb + bcol + bj;
            CP_ASYNC16(bb + (uint32_t)(row * BW + bj) * 4u, gp);
        }
        CP_COMMIT();
    };

    issue(0, 0);
    issue(1, 1);

    for (int c = 0; c < NC; c++) {
        if (c + 1 < NC) { CP_WAIT1(); } else { CP_WAIT0(); }
        __syncthreads();

        if (c + 2 < NC) issue((c + 2) % 3, c + 2);

        const uint32_t* As = (const uint32_t*)smu + (c % 3) * STG;
        const uint32_t* Bs = As + ASTG;
        #pragma unroll
        for (int k8 = 0; k8 < 4; k8++) {
            const int kk = k8 * 8 + tig;
            uint32_t a[4][4], b[4][2];
            #pragma unroll
            for (int mt = 0; mt < 4; mt++) {
                const int m0 = mb + mt * 16 + gid;
                a[mt][0] = As[m0 * AW + kk];
                a[mt][1] = As[(m0 + 8) * AW + kk];
                a[mt][2] = As[m0 * AW + kk + 4];
                a[mt][3] = As[(m0 + 8) * AW + kk + 4];
            }
            #pragma unroll
            for (int nt = 0; nt < 4; nt++) {
                const int cn = nb + nt * 8 + gid;
                b[nt][0] = Bs[kk * BW + cn];
                b[nt][1] = Bs[(kk + 4) * BW + cn];
            }
            #pragma unroll
            for (int mt = 0; mt < 4; mt++)
                #pragma unroll
                for (int nt = 0; nt < 4; nt++)
                    mma16n8k8(acc[mt][nt], a[mt], b[nt]);
        }
    }

    #pragma unroll
    for (int mt = 0; mt < 4; mt++) {
        const int row0 = rowBase + mb + mt * 16 + gid;
        const int row1 = row0 + 8;
        #pragma unroll
        for (int nt = 0; nt < 4; nt++) {
            const int jc  = nb + nt * 8 + tig * 2;
            const int col = ccol + jc;
            const float b0 = biasBlk[jc], b1 = biasBlk[jc + 1];
            float v0 = acc[mt][nt][0] + b0;
            float v1 = acc[mt][nt][1] + b1;
            float v2 = acc[mt][nt][2] + b0;
            float v3 = acc[mt][nt][3] + b1;
            if (EPI == 1) {
                const float* rp0 = res + (size_t)row0 * ldc + col;
                const float* rp1 = res + (size_t)row1 * ldc + col;
                v0 += rp0[0]; v1 += rp0[1];
                v2 += rp1[0]; v3 += rp1[1];
            }
            if (EPI == 2) {
                v0 = gelu_exact(v0); v1 = gelu_exact(v1);
                v2 = gelu_exact(v2); v3 = gelu_exact(v3);
            }
            if (EPI == 0 || EPI == 2) {
                v0 = tf32r(v0); v1 = tf32r(v1);
                v2 = tf32r(v2); v3 = tf32r(v3);
            }
            *(float2*)(C + (size_t)row0 * ldc + col) = make_float2(v0, v1);
            *(float2*)(C + (size_t)row1 * ldc + col) = make_float2(v2, v3);
        }
    }
}

template<int EPI>
__global__ __launch_bounds__(256, 2) void gemm_mma(
    const float* __restrict__ A, const float* __restrict__ B, int ldb,
    const float* __restrict__ bias, const float* __restrict__ res,
    float* __restrict__ C, int ldc, int K)
{
    const int bcol = blockIdx.x * 128;
    mma_gemm_body<EPI>(A, B, ldb, bcol, bias + bcol, res, C, ldc, bcol, K);
}

__global__ __launch_bounds__(256, 2) void qkv_mma(
    const float* __restrict__ x,
    const float* __restrict__ wq, const float* __restrict__ bq,
    const float* __restrict__ wk, const float* __restrict__ bk,
    const float* __restrict__ wv, const float* __restrict__ bv,
    float* __restrict__ qkv)
{
    const int bx  = blockIdx.x;
    const int sel = bx >> 2;
    const float* W  = (sel == 0) ? wq : (sel == 1) ? wk : wv;
    const float* bi = (sel == 0) ? bq : (sel == 1) ? bk : bv;
    const int bcol = (bx & 3) * 128;
    mma_gemm_body<0>(x, W, DIM, bcol, bi + bcol, nullptr, qkv, QKVW, bx * 128, DIM);
}

// ---------------- tensor-core flash attention ----------------
// cp.async double-buffered K/V stages; 128 regs cap -> 2 CTAs/SM.
#define ALD 68
#define VLD 72
#define KST (64 * ALD + 64 * VLD)                  // 8960 words per K/V stage
#define ATTN_SMEM ((2 * KST + 128 * ALD) * 4)      // 106496 B
#define QSCALE 0.18033688011112042f                // 0.125 * log2(e)
#define NT (SEQ / 64)                              // 32 tiles

__global__ __launch_bounds__(256, 2) void attn_tc(
    const float* __restrict__ QKV, float* __restrict__ O)
{
    extern __shared__ uint32_t asm_[];
    const uint32_t sb = smem_u32(asm_);
    uint32_t* Ps = asm_ + 2 * KST;

    const int tid  = threadIdx.x;
    const int lane = tid & 31;
    const int wid  = tid >> 5;
    const int gid  = lane >> 2;
    const int tig  = lane & 3;
    const int bh = blockIdx.y;
    const int b  = bh >> 3;
    const int h  = bh & 7;
    const int q0 = blockIdx.x * 128;

    const float* base = QKV + (size_t)b * SEQ * QKVW + (size_t)h * HDIM;
    const float* Qb = base;
    const float* Kb = base + DIM;
    const float* Vb = base + 2 * DIM;

    // Q fragments: scale folded + RNA re-round (once)
    uint32_t qa[8][4];
    {
        const float* qr0 = Qb + (size_t)(q0 + wid * 16 + gid) * QKVW;
        const float* qr1 = qr0 + (size_t)8 * QKVW;
        #pragma unroll
        for (int ks = 0; ks < 8; ks++) {
            const int c = ks * 8 + tig;
            qa[ks][0] = f2tf(qr0[c] * QSCALE);
            qa[ks][1] = f2tf(qr1[c] * QSCALE);
            qa[ks][2] = f2tf(qr0[c + 4] * QSCALE);
            qa[ks][3] = f2tf(qr1[c + 4] * QSCALE);
        }
    }

    float o[8][4];
    #pragma unroll
    for (int i = 0; i < 8; i++)
        #pragma unroll
        for (int j = 0; j < 4; j++) o[i][j] = 0.0f;
    float m0 = -1e30f, m1 = -1e30f, l0 = 0.0f, l1 = 0.0f;

    // K/V cp.async mapping: thread -> key row tid>>2, 16 floats (4 x 16B)
    const int kr = tid >> 2;
    const int dc = (tid & 3) * 16;
    const size_t KVSTEP = (size_t)64 * QKVW;
    const float* kpb = Kb + (size_t)kr * QKVW + dc;
    const float* vpb = Vb + (size_t)kr * QKVW + dc;

    auto issue = [&](int s, int t) {
        const uint32_t kb_s = sb + (uint32_t)(s * KST) * 4u;
        const uint32_t vb_s = kb_s + (uint32_t)(64 * ALD) * 4u;
        const float* kp = kpb + (size_t)t * KVSTEP;
        const float* vp = vpb + (size_t)t * KVSTEP;
        #pragma unroll
        for (int i = 0; i < 4; i++)
            CP_ASYNC16(kb_s + (uint32_t)(kr * ALD + dc + i * 4) * 4u, kp + i * 4);
        #pragma unroll
        for (int i = 0; i < 4; i++)
            CP_ASYNC16(vb_s + (uint32_t)(kr * VLD + dc + i * 4) * 4u, vp + i * 4);
        CP_COMMIT();
    };

    uint32_t* Pw = Ps + (wid * 16) * ALD;

    issue(0, 0);

    for (int t = 0; t < NT; t++) {
        CP_WAIT0();
        __syncthreads();   // stage t%2 data visible; stage (t+1)%2 fully consumed
        if (t + 1 < NT) issue((t + 1) & 1, t + 1);   // copy overlaps compute below

        const uint32_t* Ks = asm_ + (t & 1) * KST;
        const uint32_t* Vs = Ks + 64 * ALD;

        // S = Q @ K^T
        float s[8][4];
        #pragma unroll
        for (int i = 0; i < 8; i++)
            #pragma unroll
            for (int j = 0; j < 4; j++) s[i][j] = 0.0f;
        #pragma unroll
        for (int ks = 0; ks < 8; ks++) {
            const int d = ks * 8 + tig;
            #pragma unroll
            for (int nt = 0; nt < 8; nt++) {
                const int key = nt * 8 + gid;
                uint32_t bf[2] = { Ks[key * ALD + d], Ks[key * ALD + d + 4] };
                mma16n8k8(s[nt], qa[ks], bf);
            }
        }

        // base-2 online softmax
        float cm0 = -1e30f, cm1 = -1e30f;
        #pragma unroll
        for (int nt = 0; nt < 8; nt++) {
            cm0 = fmaxf(cm0, fmaxf(s[nt][0], s[nt][1]));
            cm1 = fmaxf(cm1, fmaxf(s[nt][2], s[nt][3]));
        }
        cm0 = fmaxf(cm0, __shfl_xor_sync(0xffffffffu, cm0, 1));
        cm0 = fmaxf(cm0, __shfl_xor_sync(0xffffffffu, cm0, 2));
        cm1 = fmaxf(cm1, __shfl_xor_sync(0xffffffffu, cm1, 1));
        cm1 = fmaxf(cm1, __shfl_xor_sync(0xffffffffu, cm1, 2));
        const float mn0 = fmaxf(m0, cm0);
        const float mn1 = fmaxf(m1, cm1);
        const float a0 = exp2f(m0 - mn0);
        const float a1 = exp2f(m1 - mn1);
        float ls0 = 0.0f, ls1 = 0.0f;
        #pragma unroll
        for (int nt = 0; nt < 8; nt++) {
            s[nt][0] = exp2f(s[nt][0] - mn0);
            s[nt][1] = exp2f(s[nt][1] - mn0);
            s[nt][2] = exp2f(s[nt][2] - mn1);
            s[nt][3] = exp2f(s[nt][3] - mn1);
            ls0 += s[nt][0] + s[nt][1];
            ls1 += s[nt][2] + s[nt][3];
        }
        ls0 += __shfl_xor_sync(0xffffffffu, ls0, 1);
        ls0 += __shfl_xor_sync(0xffffffffu, ls0, 2);
        ls1 += __shfl_xor_sync(0xffffffffu, ls1, 1);
        ls1 += __shfl_xor_sync(0xffffffffu, ls1, 2);
        l0 = l0 * a0 + ls0;
        l1 = l1 * a1 + ls1;
        m0 = mn0; m1 = mn1;
        #pragma unroll
        for (int nt = 0; nt < 8; nt++) {
            o[nt][0] *= a0; o[nt][1] *= a0;
            o[nt][2] *= a1; o[nt][3] *= a1;
        }

        // P (RNA tf32) to warp-private strip
        #pragma unroll
        for (int nt = 0; nt < 8; nt++) {
            const int c = nt * 8 + tig * 2;
            *(uint2*)&Pw[gid * ALD + c]       = make_uint2(f2tf(s[nt][0]), f2tf(s[nt][1]));
            *(uint2*)&Pw[(gid + 8) * ALD + c] = make_uint2(f2tf(s[nt][2]), f2tf(s[nt][3]));
        }
        __syncwarp();

        // O += P @ V
        #pragma unroll
        for (int ks = 0; ks < 8; ks++) {
            const int kk = ks * 8 + tig;
            uint32_t pa[4];
            pa[0] = Pw[gid * ALD + kk];
            pa[1] = Pw[(gid + 8) * ALD + kk];
            pa[2] = Pw[gid * ALD + kk + 4];
            pa[3] = Pw[(gid + 8) * ALD + kk + 4];
            #pragma unroll
            for (int nt = 0; nt < 8; nt++) {
                const int dn = nt * 8 + gid;
                uint32_t bf[2] = { Vs[kk * VLD + dn], Vs[(kk + 4) * VLD + dn] };
                mma16n8k8(o[nt], pa, bf);
            }
        }
    }

    const float i0 = 1.0f / l0;
    const float i1 = 1.0f / l1;
    const int row0 = q0 + wid * 16 + gid;
    float* Ob0 = O + (size_t)(b * SEQ + row0) * DIM + h * HDIM;
    float* Ob1 = Ob0 + (size_t)8 * DIM;
    #pragma unroll
    for (int nt = 0; nt < 8; nt++) {
        const int c = nt * 8 + tig * 2;
        *(float2*)(Ob0 + c) = make_float2(tf32r(o[nt][0] * i0), tf32r(o[nt][1] * i0));
        *(float2*)(Ob1 + c) = make_float2(tf32r(o[nt][2] * i1), tf32r(o[nt][3] * i1));
    }
}

// ---------------- layernorm ----------------
template<int RND>
__global__ __launch_bounds__(256) void ln_kernel(
    const float* __restrict__ x, const float* __restrict__ g,
    const float* __restrict__ be, float* __restrict__ out)
{
    const int row = blockIdx.x;
    const int t = threadIdx.x;
    const float* xr = x + (size_t)row * DIM;
    float v0 = xr[t], v1 = xr[t + 256];
    float s = v0 + v1, sq = v0 * v0 + v1 * v1;
    #pragma unroll
    for (int o = 16; o > 0; o >>= 1) {
        s  += __shfl_xor_sync(0xffffffffu, s, o);
        sq += __shfl_xor_sync(0xffffffffu, sq, o);
    }
    __shared__ float ps[8], pq[8];
    __shared__ float mu_s, inv_s;
    if ((t & 31) == 0) { ps[t >> 5] = s; pq[t >> 5] = sq; }
    __syncthreads();
    if (t == 0) {
        float S = 0.0f, Qq = 0.0f;
        #pragma unroll
        for (int i = 0; i < 8; i++) { S += ps[i]; Qq += pq[i]; }
        float mu = S * (1.0f / DIM);
        float var = Qq * (1.0f / DIM) - mu * mu;
        mu_s = mu;
        inv_s = rsqrtf(var + 1e-5f);
    }
    __syncthreads();
    float mu = mu_s, inv = inv_s;
    float w0 = (v0 - mu) * inv * g[t]       + be[t];
    float w1 = (v1 - mu) * inv * g[t + 256] + be[t + 256];
    if (RND) { w0 = tf32r(w0); w1 = tf32r(w1); }
    out[(size_t)row * DIM + t]       = w0;
    out[(size_t)row * DIM + t + 256] = w1;
}

// ---------------- launch ----------------
extern "C" void kernel_launch(void* const* d_in, const int* in_sizes, int n_in,
                              void* d_out, int out_size)
{
    const float* x   = (const float*)d_in[0];
    const float* wq  = (const float*)d_in[1];
    const float* bq  = (const float*)d_in[2];
    const float* wk  = (const float*)d_in[3];
    const float* bk  = (const float*)d_in[4];
    const float* wv  = (const float*)d_in[5];
    const float* bv  = (const float*)d_in[6];
    const float* wo  = (const float*)d_in[7];
    const float* bo  = (const float*)d_in[8];
    const float* w1  = (const float*)d_in[9];
    const float* b1  = (const float*)d_in[10];
    const float* w2  = (const float*)d_in[11];
    const float* b2  = (const float*)d_in[12];
    const float* g1  = (const float*)d_in[13];
    const float* be1 = (const float*)d_in[14];
    const float* g2  = (const float*)d_in[15];
    const float* be2 = (const float*)d_in[16];
    float* out = (float*)d_out;

    float *qkv, *att, *y1, *x1, *hbuf, *y2;
    float *xr, *wqr, *wkr, *wvr, *wor, *w1r, *w2r;
    cudaGetSymbolAddress((void**)&qkv,  g_qkv);
    cudaGetSymbolAddress((void**)&att,  g_att);
    cudaGetSymbolAddress((void**)&y1,   g_y1);
    cudaGetSymbolAddress((void**)&x1,   g_x1);
    cudaGetSymbolAddress((void**)&hbuf, g_h);
    cudaGetSymbolAddress((void**)&y2,   g_y2);
    cudaGetSymbolAddress((void**)&xr,   g_xr);
    cudaGetSymbolAddress((void**)&wqr,  g_wqr);
    cudaGetSymbolAddress((void**)&wkr,  g_wkr);
    cudaGetSymbolAddress((void**)&wvr,  g_wvr);
    cudaGetSymbolAddress((void**)&wor,  g_wor);
    cudaGetSymbolAddress((void**)&w1r,  g_w1r);
    cudaGetSymbolAddress((void**)&w2r,  g_w2r);

    cudaFuncSetAttribute(attn_tc,
                         cudaFuncAttributeMaxDynamicSharedMemorySize, ATTN_SMEM);
    cudaFuncSetAttribute(qkv_mma,
                         cudaFuncAttributeMaxDynamicSharedMemorySize, GEMM_SMEM);
    cudaFuncSetAttribute(gemm_mma<1>,
                         cudaFuncAttributeMaxDynamicSharedMemorySize, GEMM_SMEM);
    cudaFuncSetAttribute(gemm_mma<2>,
                         cudaFuncAttributeMaxDynamicSharedMemorySize, GEMM_SMEM);

    // pre-round all GEMM operands (RNA tf32): 2 launches
    round_x_kernel<<<(MTOT * DIM / 4 + 255) / 256, 256>>>(x, xr, MTOT * DIM / 4);
    round_w_kernel<<<(4 * W44 + 2 * WF4 + 255) / 256, 256>>>(
        wq, wk, wv, wo, w1, w2, wqr, wkr, wvr, wor, w1r, w2r);

    const int MB = MTOT / 128;   // 64

    // fused QKV projection (output rounded in epilogue)
    qkv_mma<<<dim3(12, MB), 256, GEMM_SMEM>>>(xr, wqr, bq, wkr, bk, wvr, bv, qkv);

    // tensor-core flash attention (2 CTAs/SM)
    attn_tc<<<dim3(SEQ / 128, BATCH * NHEAD), 256, ATTN_SMEM>>>(qkv, att);

    // output projection + residual (res = ORIGINAL x), LN1 (rounds x1)
    gemm_mma<1><<<dim3(DIM / 128, MB), 256, GEMM_SMEM>>>(
        att, wor, DIM, bo, x, y1, DIM, DIM);
    ln_kernel<1><<<MTOT, 256>>>(y1, g1, be1, x1);

    // FFN
    gemm_mma<2><<<dim3(FFN / 128, MB), 256, GEMM_SMEM>>>(
        x1, w1r, FFN, b1, nullptr, hbuf, FFN, DIM);
    gemm_mma<1><<<dim3(DIM / 128, MB), 256, GEMM_SMEM>>>(
        hbuf, w2r, DIM, b2, x1, y2, DIM, FFN);
    ln_kernel<0><<<MTOT, 256>>>(y2, g2, be2, out);
}

// round 17
// speedup vs baseline: 1.2637x; 1.1846x over previous
#include <cuda_runtime.h>
#include <cuda_fp16.h>
#include <math.h>
#include <stdint.h>

// ---------------- problem constants ----------------
#define BATCH 4
#define SEQ   2048
#define DIM   512
#define NHEAD 8
#define HDIM  64
#define FFN   2048
#define MTOT  (BATCH * SEQ)          // 8192 rows
#define QKVW  (3 * DIM)              // 1536

// ---------------- scratch (no allocation allowed) ----------------
__device__ float  g_qkv [MTOT * QKVW];     // fp32 (tf32-rounded) for attention
__device__ __half g_att [MTOT * DIM];
__device__ float  g_y1  [MTOT * DIM];
__device__ float  g_x1f [MTOT * DIM];      // LN1 out fp32 (residual for y2)
__device__ __half g_x1h [MTOT * DIM];      // LN1 out half (GEMM A)
__device__ __half g_h   [MTOT * FFN];
__device__ float  g_y2  [MTOT * DIM];
__device__ __half g_xh  [MTOT * DIM];      // half(x)
__device__ __half g_wqt [DIM * DIM];       // W^T half [N][K]
__device__ __half g_wkt [DIM * DIM];
__device__ __half g_wvt [DIM * DIM];
__device__ __half g_wot [DIM * DIM];
__device__ __half g_w1t [FFN * DIM];       // [2048][512]
__device__ __half g_w2t [DIM * FFN];       // [512][2048]

// ---------------- helpers ----------------
__device__ __forceinline__ uint32_t smem_u32(const void* p) {
    uint32_t a;
    asm("{ .reg .u64 t; cvta.to.shared.u64 t, %1; cvt.u32.u64 %0, t; }"
        : "=r"(a) : "l"(p));
    return a;
}
__device__ __forceinline__ uint32_t f2tf(float x) {
    uint32_t r;
    asm("cvt.rna.tf32.f32 %0, %1;" : "=r"(r) : "f"(x));
    return r;
}
__device__ __forceinline__ float tf32r(float x) {
    return __uint_as_float(f2tf(x));
}
__device__ __forceinline__ float gelu_exact(float v) {
    return 0.5f * v * (1.0f + erff(v * 0.70710678118654752f));
}
// tf32 m16n8k8 (attention)
__device__ __forceinline__ void mma16n8k8(float* c, const uint32_t* a, const uint32_t* b) {
    asm volatile(
        "mma.sync.aligned.m16n8k8.row.col.f32.tf32.tf32.f32 "
        "{%0,%1,%2,%3}, {%4,%5,%6,%7}, {%8,%9}, {%0,%1,%2,%3};"
        : "+f"(c[0]), "+f"(c[1]), "+f"(c[2]), "+f"(c[3])
        : "r"(a[0]), "r"(a[1]), "r"(a[2]), "r"(a[3]), "r"(b[0]), "r"(b[1]));
}
// fp16 m16n8k16 (GEMMs)
__device__ __forceinline__ void mma16n8k16h(float* c, const uint32_t* a, const uint32_t* b) {
    asm volatile(
        "mma.sync.aligned.m16n8k16.row.col.f32.f16.f16.f32 "
        "{%0,%1,%2,%3}, {%4,%5,%6,%7}, {%8,%9}, {%0,%1,%2,%3};"
        : "+f"(c[0]), "+f"(c[1]), "+f"(c[2]), "+f"(c[3])
        : "r"(a[0]), "r"(a[1]), "r"(a[2]), "r"(a[3]), "r"(b[0]), "r"(b[1]));
}

#define CP_ASYNC16(saddr, gptr) \
    asm volatile("cp.async.cg.shared.global [%0], [%1], 16;" \
                 :: "r"(saddr), "l"(gptr) : "memory")
#define CP_COMMIT() asm volatile("cp.async.commit_group;" ::: "memory")
#define CP_WAIT1()  asm volatile("cp.async.wait_group 1;" ::: "memory")
#define CP_WAIT0()  asm volatile("cp.async.wait_group 0;" ::: "memory")

// ---------------- input transforms ----------------
__global__ __launch_bounds__(256) void conv_x_kernel(
    const float* __restrict__ src, __half* __restrict__ dst, int n4)
{
    int i = blockIdx.x * 256 + threadIdx.x;
    if (i < n4) {
        float4 v = ((const float4*)src)[i];
        __half2 h0 = __floats2half2_rn(v.x, v.y);
        __half2 h1 = __floats2half2_rn(v.z, v.w);
        ((uint2*)dst)[i] = make_uint2(*(uint32_t*)&h0, *(uint32_t*)&h1);
    }
}

// W[K][N] fp32 -> Wt[N][K] half
__global__ __launch_bounds__(256) void transh_kernel(
    const float* __restrict__ W, __half* __restrict__ Wt, int K, int N)
{
    __shared__ float t[32][33];
    const int nb = blockIdx.x * 32, kb = blockIdx.y * 32;
    const int tx = threadIdx.x & 31, ty = (threadIdx.x >> 5) * 4;
    #pragma unroll
    for (int i = 0; i < 4; i++)
        t[ty + i][tx] = W[(size_t)(kb + ty + i) * N + nb + tx];
    __syncthreads();
    #pragma unroll
    for (int i = 0; i < 4; i++)
        Wt[(size_t)(nb + ty + i) * K + kb + tx] = __float2half_rn(t[tx][ty + i]);
}

// ---------------- fp16 mma.sync GEMM, 3-stage cp.async ----------------
// A smem: [128 m][40 k-halves] ; B smem: [128 n][40 k-halves] (Bt is [N][K])
#define AWH 40
#define ASTGH (128 * AWH)           // 5120 halves
#define STGH  (2 * ASTGH)           // 10240 halves per stage
#define GEMM_SMEM (3 * STGH * 2)    // 61440 bytes

// EPI: 0 = bias, fp32 out (tf32-rounded, feeds attention)
//      1 = bias + fp32 residual, fp32 out
//      2 = bias + gelu, half out
template<int EPI>
__device__ __forceinline__ void mma_gemm_body(
    const __half* __restrict__ A,
    const __half* __restrict__ Bt, int bcol,     // Bt[N][K], rows bcol..+127
    const float* __restrict__ biasBlk,
    const float* __restrict__ res,
    void* __restrict__ Cout, int ldc, int ccol,
    int K)
{
    extern __shared__ __half smh[];
    const uint32_t sb = smem_u32(smh);

    const int tid  = threadIdx.x;
    const int lane = tid & 31;
    const int wid  = tid >> 5;
    const int gid  = lane >> 2;
    const int tig  = lane & 3;
    const int rowBase = blockIdx.y * 128;
    const int mb = (wid & 1) * 64;
    const int nb = (wid >> 1) * 32;

    // cp.async mapping: thread -> row tid>>1, halves (tid&1)*16 .. +15 (2x16B)
    const int crow = tid >> 1;
    const int choff = (tid & 1) * 16;

    float acc[4][4][4];
    #pragma unroll
    for (int i = 0; i < 4; i++)
        #pragma unroll
        for (int j = 0; j < 4; j++)
            #pragma unroll
            for (int e = 0; e < 4; e++) acc[i][j][e] = 0.0f;

    const int NC = K >> 5;   // 32 halves of K per chunk

    const __half* apB = A  + (size_t)(rowBase + crow) * K + choff;
    const __half* bpB = Bt + (size_t)(bcol + crow) * K + choff;

    auto issue = [&](int s, int c) {
        const uint32_t ab = sb + (uint32_t)(s * STGH) * 2u;
        const uint32_t bb = ab + (uint32_t)ASTGH * 2u;
        const __half* ga = apB + c * 32;
        const __half* gb = bpB + c * 32;
        const uint32_t so = (uint32_t)(crow * AWH + choff) * 2u;
        CP_ASYNC16(ab + so,      ga);
        CP_ASYNC16(ab + so + 16, ga + 8);
        CP_ASYNC16(bb + so,      gb);
        CP_ASYNC16(bb + so + 16, gb + 8);
        CP_COMMIT();
    };

    issue(0, 0);
    issue(1, 1);

    for (int c = 0; c < NC; c++) {
        if (c + 1 < NC) { CP_WAIT1(); } else { CP_WAIT0(); }
        __syncthreads();                     // chunk c visible; buffer (c+2)%3 free

        if (c + 2 < NC) issue((c + 2) % 3, c + 2);

        const __half* As = smh + (c % 3) * STGH;
        const __half* Bs = As + ASTGH;
        #pragma unroll
        for (int ks = 0; ks < 2; ks++) {     // two k16 steps per chunk
            const int k0 = ks * 16 + 2 * tig;
            uint32_t a[4][4], b[4][2];
            #pragma unroll
            for (int mt = 0; mt < 4; mt++) {
                const int m0 = mb + mt * 16 + gid;
                a[mt][0] = *(const uint32_t*)&As[m0 * AWH + k0];
                a[mt][1] = *(const uint32_t*)&As[(m0 + 8) * AWH + k0];
                a[mt][2] = *(const uint32_t*)&As[m0 * AWH + k0 + 8];
                a[mt][3] = *(const uint32_t*)&As[(m0 + 8) * AWH + k0 + 8];
            }
            #pragma unroll
            for (int nt = 0; nt < 4; nt++) {
                const int cn = nb + nt * 8 + gid;
                b[nt][0] = *(const uint32_t*)&Bs[cn * AWH + k0];
                b[nt][1] = *(const uint32_t*)&Bs[cn * AWH + k0 + 8];
            }
            #pragma unroll
            for (int mt = 0; mt < 4; mt++)
                #pragma unroll
                for (int nt = 0; nt < 4; nt++)
                    mma16n8k16h(acc[mt][nt], a[mt], b[nt]);
        }
    }

    // epilogue
    #pragma unroll
    for (int mt = 0; mt < 4; mt++) {
        const int row0 = rowBase + mb + mt * 16 + gid;
        const int row1 = row0 + 8;
        #pragma unroll
        for (int nt = 0; nt < 4; nt++) {
            const int jc  = nb + nt * 8 + tig * 2;
            const int col = ccol + jc;
            const float b0 = biasBlk[jc], b1 = biasBlk[jc + 1];
            float v0 = acc[mt][nt][0] + b0;
            float v1 = acc[mt][nt][1] + b1;
            float v2 = acc[mt][nt][2] + b0;
            float v3 = acc[mt][nt][3] + b1;
            if (EPI == 1) {
                const float* rp0 = res + (size_t)row0 * ldc + col;
                const float* rp1 = res + (size_t)row1 * ldc + col;
                v0 += rp0[0]; v1 += rp0[1];
                v2 += rp1[0]; v3 += rp1[1];
                float* C = (float*)Cout;
                *(float2*)(C + (size_t)row0 * ldc + col) = make_float2(v0, v1);
                *(float2*)(C + (size_t)row1 * ldc + col) = make_float2(v2, v3);
            }
            if (EPI == 0) {   // fp32 out, tf32-rounded (attention input)
                float* C = (float*)Cout;
                *(float2*)(C + (size_t)row0 * ldc + col) =
                    make_float2(tf32r(v0), tf32r(v1));
                *(float2*)(C + (size_t)row1 * ldc + col) =
                    make_float2(tf32r(v2), tf32r(v3));
            }
            if (EPI == 2) {   // gelu, half out
                __half* C = (__half*)Cout;
                *(__half2*)(C + (size_t)row0 * ldc + col) =
                    __floats2half2_rn(gelu_exact(v0), gelu_exact(v1));
                *(__half2*)(C + (size_t)row1 * ldc + col) =
                    __floats2half2_rn(gelu_exact(v2), gelu_exact(v3));
            }
        }
    }
}

template<int EPI>
__global__ __launch_bounds__(256, 2) void gemm_mma(
    const __half* __restrict__ A, const __half* __restrict__ Bt,
    const float* __restrict__ bias, const float* __restrict__ res,
    void* __restrict__ C, int ldc, int K)
{
    const int bcol = blockIdx.x * 128;
    mma_gemm_body<EPI>(A, Bt, bcol, bias + bcol, res, C, ldc, bcol, K);
}

__global__ __launch_bounds__(256, 2) void qkv_mma(
    const __half* __restrict__ x,
    const __half* __restrict__ wqt, const float* __restrict__ bq,
    const __half* __restrict__ wkt, const float* __restrict__ bk,
    const __half* __restrict__ wvt, const float* __restrict__ bv,
    float* __restrict__ qkv)
{
    const int bx  = blockIdx.x;
    const int sel = bx >> 2;
    const __half* W = (sel == 0) ? wqt : (sel == 1) ? wkt : wvt;
    const float* bi = (sel == 0) ? bq  : (sel == 1) ? bk  : bv;
    const int bcol = (bx & 3) * 128;
    mma_gemm_body<0>(x, W, bcol, bi + bcol, nullptr, qkv, QKVW, bx * 128, DIM);
}

// ---------------- tensor-core flash attention (tf32, unchanged core) --------
#define ALD 68
#define VLD 72
#define KST (64 * ALD + 64 * VLD)                  // 8960 words per K/V stage
#define ATTN_SMEM ((2 * KST + 128 * ALD) * 4)      // 106496 B
#define QSCALE 0.18033688011112042f                // 0.125 * log2(e)
#define NT (SEQ / 64)

__global__ __launch_bounds__(256, 2) void attn_tc(
    const float* __restrict__ QKV, __half* __restrict__ O)
{
    extern __shared__ uint32_t asm_[];
    const uint32_t sb = smem_u32(asm_);
    uint32_t* Ps = asm_ + 2 * KST;

    const int tid  = threadIdx.x;
    const int lane = tid & 31;
    const int wid  = tid >> 5;
    const int gid  = lane >> 2;
    const int tig  = lane & 3;
    const int bh = blockIdx.y;
    const int b  = bh >> 3;
    const int h  = bh & 7;
    const int q0 = blockIdx.x * 128;

    const float* base = QKV + (size_t)b * SEQ * QKVW + (size_t)h * HDIM;
    const float* Qb = base;
    const float* Kb = base + DIM;
    const float* Vb = base + 2 * DIM;

    uint32_t qa[8][4];
    {
        const float* qr0 = Qb + (size_t)(q0 + wid * 16 + gid) * QKVW;
        const float* qr1 = qr0 + (size_t)8 * QKVW;
        #pragma unroll
        for (int ks = 0; ks < 8; ks++) {
            const int c = ks * 8 + tig;
            qa[ks][0] = f2tf(qr0[c] * QSCALE);
            qa[ks][1] = f2tf(qr1[c] * QSCALE);
            qa[ks][2] = f2tf(qr0[c + 4] * QSCALE);
            qa[ks][3] = f2tf(qr1[c + 4] * QSCALE);
        }
    }

    float o[8][4];
    #pragma unroll
    for (int i = 0; i < 8; i++)
        #pragma unroll
        for (int j = 0; j < 4; j++) o[i][j] = 0.0f;
    float m0 = -1e30f, m1 = -1e30f, l0 = 0.0f, l1 = 0.0f;

    const int kr = tid >> 2;
    const int dc = (tid & 3) * 16;
    const size_t KVSTEP = (size_t)64 * QKVW;
    const float* kpb = Kb + (size_t)kr * QKVW + dc;
    const float* vpb = Vb + (size_t)kr * QKVW + dc;

    auto issue = [&](int s, int t) {
        const uint32_t kb_s = sb + (uint32_t)(s * KST) * 4u;
        const uint32_t vb_s = kb_s + (uint32_t)(64 * ALD) * 4u;
        const float* kp = kpb + (size_t)t * KVSTEP;
        const float* vp = vpb + (size_t)t * KVSTEP;
        #pragma unroll
        for (int i = 0; i < 4; i++)
            CP_ASYNC16(kb_s + (uint32_t)(kr * ALD + dc + i * 4) * 4u, kp + i * 4);
        #pragma unroll
        for (int i = 0; i < 4; i++)
            CP_ASYNC16(vb_s + (uint32_t)(kr * VLD + dc + i * 4) * 4u, vp + i * 4);
        CP_COMMIT();
    };

    uint32_t* Pw = Ps + (wid * 16) * ALD;

    issue(0, 0);

    for (int t = 0; t < NT; t++) {
        CP_WAIT0();
        __syncthreads();
        if (t + 1 < NT) issue((t + 1) & 1, t + 1);

        const uint32_t* Ks = asm_ + (t & 1) * KST;
        const uint32_t* Vs = Ks + 64 * ALD;

        float s[8][4];
        #pragma unroll
        for (int i = 0; i < 8; i++)
            #pragma unroll
            for (int j = 0; j < 4; j++) s[i][j] = 0.0f;
        #pragma unroll
        for (int ks = 0; ks < 8; ks++) {
            const int d = ks * 8 + tig;
            #pragma unroll
            for (int nt = 0; nt < 8; nt++) {
                const int key = nt * 8 + gid;
                uint32_t bf[2] = { Ks[key * ALD + d], Ks[key * ALD + d + 4] };
                mma16n8k8(s[nt], qa[ks], bf);
            }
        }

        float cm0 = -1e30f, cm1 = -1e30f;
        #pragma unroll
        for (int nt = 0; nt < 8; nt++) {
            cm0 = fmaxf(cm0, fmaxf(s[nt][0], s[nt][1]));
            cm1 = fmaxf(cm1, fmaxf(s[nt][2], s[nt][3]));
        }
        cm0 = fmaxf(cm0, __shfl_xor_sync(0xffffffffu, cm0, 1));
        cm0 = fmaxf(cm0, __shfl_xor_sync(0xffffffffu, cm0, 2));
        cm1 = fmaxf(cm1, __shfl_xor_sync(0xffffffffu, cm1, 1));
        cm1 = fmaxf(cm1, __shfl_xor_sync(0xffffffffu, cm1, 2));
        const float mn0 = fmaxf(m0, cm0);
        const float mn1 = fmaxf(m1, cm1);
        const float a0 = exp2f(m0 - mn0);
        const float a1 = exp2f(m1 - mn1);
        float ls0 = 0.0f, ls1 = 0.0f;
        #pragma unroll
        for (int nt = 0; nt < 8; nt++) {
            s[nt][0] = exp2f(s[nt][0] - mn0);
            s[nt][1] = exp2f(s[nt][1] - mn0);
            s[nt][2] = exp2f(s[nt][2] - mn1);
            s[nt][3] = exp2f(s[nt][3] - mn1);
            ls0 += s[nt][0] + s[nt][1];
            ls1 += s[nt][2] + s[nt][3];
        }
        ls0 += __shfl_xor_sync(0xffffffffu, ls0, 1);
        ls0 += __shfl_xor_sync(0xffffffffu, ls0, 2);
        ls1 += __shfl_xor_sync(0xffffffffu, ls1, 1);
        ls1 += __shfl_xor_sync(0xffffffffu, ls1, 2);
        l0 = l0 * a0 + ls0;
        l1 = l1 * a1 + ls1;
        m0 = mn0; m1 = mn1;
        #pragma unroll
        for (int nt = 0; nt < 8; nt++) {
            o[nt][0] *= a0; o[nt][1] *= a0;
            o[nt][2] *= a1; o[nt][3] *= a1;
        }

        #pragma unroll
        for (int nt = 0; nt < 8; nt++) {
            const int c = nt * 8 + tig * 2;
            *(uint2*)&Pw[gid * ALD + c]       = make_uint2(f2tf(s[nt][0]), f2tf(s[nt][1]));
            *(uint2*)&Pw[(gid + 8) * ALD + c] = make_uint2(f2tf(s[nt][2]), f2tf(s[nt][3]));
        }
        __syncwarp();

        #pragma unroll
        for (int ks = 0; ks < 8; ks++) {
            const int kk = ks * 8 + tig;
            uint32_t pa[4];
            pa[0] = Pw[gid * ALD + kk];
            pa[1] = Pw[(gid + 8) * ALD + kk];
            pa[2] = Pw[gid * ALD + kk + 4];
            pa[3] = Pw[(gid + 8) * ALD + kk + 4];
            #pragma unroll
            for (int nt = 0; nt < 8; nt++) {
                const int dn = nt * 8 + gid;
                uint32_t bf[2] = { Vs[kk * VLD + dn], Vs[(kk + 4) * VLD + dn] };
                mma16n8k8(o[nt], pa, bf);
            }
        }
    }

    const float i0 = 1.0f / l0;
    const float i1 = 1.0f / l1;
    const int row0 = q0 + wid * 16 + gid;
    __half* Ob0 = O + (size_t)(b * SEQ + row0) * DIM + h * HDIM;
    __half* Ob1 = Ob0 + (size_t)8 * DIM;
    #pragma unroll
    for (int nt = 0; nt < 8; nt++) {
        const int c = nt * 8 + tig * 2;
        *(__half2*)(Ob0 + c) = __floats2half2_rn(o[nt][0] * i0, o[nt][1] * i0);
        *(__half2*)(Ob1 + c) = __floats2half2_rn(o[nt][2] * i1, o[nt][3] * i1);
    }
}

// ---------------- layernorm ----------------
// MODE 0: fp32 out only (final). MODE 1: fp32 out + half out (mid-layer).
template<int MODE>
__global__ __launch_bounds__(256) void ln_kernel(
    const float* __restrict__ x, const float* __restrict__ g,
    const float* __restrict__ be, float* __restrict__ outf,
    __half* __restrict__ outh)
{
    const int row = blockIdx.x;
    const int t = threadIdx.x;
    const float* xr = x + (size_t)row * DIM;
    float v0 = xr[t], v1 = xr[t + 256];
    float s = v0 + v1, sq = v0 * v0 + v1 * v1;
    #pragma unroll
    for (int o = 16; o > 0; o >>= 1) {
        s  += __shfl_xor_sync(0xffffffffu, s, o);
        sq += __shfl_xor_sync(0xffffffffu, sq, o);
    }
    __shared__ float ps[8], pq[8];
    __shared__ float mu_s, inv_s;
    if ((t & 31) == 0) { ps[t >> 5] = s; pq[t >> 5] = sq; }
    __syncthreads();
    if (t == 0) {
        float S = 0.0f, Qq = 0.0f;
        #pragma unroll
        for (int i = 0; i < 8; i++) { S += ps[i]; Qq += pq[i]; }
        float mu = S * (1.0f / DIM);
        float var = Qq * (1.0f / DIM) - mu * mu;
        mu_s = mu;
        inv_s = rsqrtf(var + 1e-5f);
    }
    __syncthreads();
    float mu = mu_s, inv = inv_s;
    float w0 = (v0 - mu) * inv * g[t]       + be[t];
    float w1 = (v1 - mu) * inv * g[t + 256] + be[t + 256];
    outf[(size_t)row * DIM + t]       = w0;
    outf[(size_t)row * DIM + t + 256] = w1;
    if (MODE == 1) {
        outh[(size_t)row * DIM + t]       = __float2half_rn(w0);
        outh[(size_t)row * DIM + t + 256] = __float2half_rn(w1);
    }
}

// ---------------- launch ----------------
extern "C" void kernel_launch(void* const* d_in, const int* in_sizes, int n_in,
                              void* d_out, int out_size)
{
    const float* x   = (const float*)d_in[0];
    const float* wq  = (const float*)d_in[1];
    const float* bq  = (const float*)d_in[2];
    const float* wk  = (const float*)d_in[3];
    const float* bk  = (const float*)d_in[4];
    const float* wv  = (const float*)d_in[5];
    const float* bv  = (const float*)d_in[6];
    const float* wo  = (const float*)d_in[7];
    const float* bo  = (const float*)d_in[8];
    const float* w1  = (const float*)d_in[9];
    const float* b1  = (const float*)d_in[10];
    const float* w2  = (const float*)d_in[11];
    const float* b2  = (const float*)d_in[12];
    const float* g1  = (const float*)d_in[13];
    const float* be1 = (const float*)d_in[14];
    const float* g2  = (const float*)d_in[15];
    const float* be2 = (const float*)d_in[16];
    float* out = (float*)d_out;

    float  *qkv, *y1, *x1f, *y2;
    __half *att, *x1h, *hbuf, *xh, *wqt, *wkt, *wvt, *wot, *w1t, *w2t;
    cudaGetSymbolAddress((void**)&qkv,  g_qkv);
    cudaGetSymbolAddress((void**)&att,  g_att);
    cudaGetSymbolAddress((void**)&y1,   g_y1);
    cudaGetSymbolAddress((void**)&x1f,  g_x1f);
    cudaGetSymbolAddress((void**)&x1h,  g_x1h);
    cudaGetSymbolAddress((void**)&hbuf, g_h);
    cudaGetSymbolAddress((void**)&y2,   g_y2);
    cudaGetSymbolAddress((void**)&xh,   g_xh);
    cudaGetSymbolAddress((void**)&wqt,  g_wqt);
    cudaGetSymbolAddress((void**)&wkt,  g_wkt);
    cudaGetSymbolAddress((void**)&wvt,  g_wvt);
    cudaGetSymbolAddress((void**)&wot,  g_wot);
    cudaGetSymbolAddress((void**)&w1t,  g_w1t);
    cudaGetSymbolAddress((void**)&w2t,  g_w2t);

    cudaFuncSetAttribute(attn_tc,
                         cudaFuncAttributeMaxDynamicSharedMemorySize, ATTN_SMEM);
    cudaFuncSetAttribute(qkv_mma,
                         cudaFuncAttributeMaxDynamicSharedMemorySize, GEMM_SMEM);
    cudaFuncSetAttribute(gemm_mma<1>,
                         cudaFuncAttributeMaxDynamicSharedMemorySize, GEMM_SMEM);
    cudaFuncSetAttribute(gemm_mma<2>,
                         cudaFuncAttributeMaxDynamicSharedMemorySize, GEMM_SMEM);

    // input transforms
    conv_x_kernel<<<(MTOT * DIM / 4 + 255) / 256, 256>>>(x, xh, MTOT * DIM / 4);
    transh_kernel<<<dim3(DIM / 32, DIM / 32), 256>>>(wq, wqt, DIM, DIM);
    transh_kernel<<<dim3(DIM / 32, DIM / 32), 256>>>(wk, wkt, DIM, DIM);
    transh_kernel<<<dim3(DIM / 32, DIM / 32), 256>>>(wv, wvt, DIM, DIM);
    transh_kernel<<<dim3(DIM / 32, DIM / 32), 256>>>(wo, wot, DIM, DIM);
    transh_kernel<<<dim3(FFN / 32, DIM / 32), 256>>>(w1, w1t, DIM, FFN);
    transh_kernel<<<dim3(DIM / 32, FFN / 32), 256>>>(w2, w2t, FFN, DIM);

    const int MB = MTOT / 128;   // 64

    // fused QKV projection -> qkv fp32 (tf32-rounded)
    qkv_mma<<<dim3(12, MB), 256, GEMM_SMEM>>>(xh, wqt, bq, wkt, bk, wvt, bv, qkv);

    // tensor-core flash attention -> att half
    attn_tc<<<dim3(SEQ / 128, BATCH * NHEAD), 256, ATTN_SMEM>>>(qkv, att);

    // output projection + residual (original fp32 x), LN1
    gemm_mma<1><<<dim3(DIM / 128, MB), 256, GEMM_SMEM>>>(
        att, wot, bo, x, y1, DIM, DIM);
    ln_kernel<1><<<MTOT, 256>>>(y1, g1, be1, x1f, x1h);

    // FFN
    gemm_mma<2><<<dim3(FFN / 128, MB), 256, GEMM_SMEM>>>(
        x1h, w1t, b1, nullptr, hbuf, FFN, DIM);
    gemm_mma<1><<<dim3(DIM / 128, MB), 256, GEMM_SMEM>>>(
        hbuf, w2t, b2, x1f, y2, DIM, FFN);
    ln_kernel<0><<<MTOT, 256>>>(y2, g2, be2, out, nullptr);
}